// round 16
// baseline (speedup 1.0000x reference)
#include <cuda_runtime.h>
#include <cuda_bf16.h>
#include <cuda_fp16.h>
#include <cstdint>

#define B_   16
#define N_   4096
#define M_   1024
#define C1_  256
#define C2_  512
#define K1_  768
#define CO_  256
#define BNR  65536
#define ZR   (B_*M_)     // 16384

#define LDA  40           // fp16 elems per A smem row (32 + 8 pad)
#define LDB  136          // fp16 elems per B smem row (128 + 8 pad)

#define A_STAGE (2*128*LDA)   // hi+lo elems per stage = 10240
#define B_STAGE (32*LDB)      // single fp16 B per stage = 4352
#define SMEM_BYTES ((2*A_STAGE + 2*B_STAGE)*2 + (128+256+256+128+128+384)*4 + 384*4)

// ---------------- scratch ---------------------------------------------------
__device__ float g_y1[BNR*CO_];
__device__ float g_y2[BNR*CO_];
__device__ float g_z [ZR*CO_];
__device__ float g_w [BNR*3];
__device__ int   g_idx[BNR*3];
__device__ __half g_W1h[K1_*CO_];    // [k][n] fp16
__device__ __half g_W2h[CO_*CO_];    // [k][n] fp16
__device__ float g_stats1[2*CO_], g_stats2[2*CO_];
__device__ float g_bn1a[CO_], g_bn1b[CO_], g_bn2a[CO_], g_bn2b[CO_];

// ---------------- helpers ---------------------------------------------------
__device__ __forceinline__ uint32_t s2u(const void* p){
    return (uint32_t)__cvta_generic_to_shared(p);
}
__device__ __forceinline__ void ldsm4(uint32_t r[4], uint32_t a){
    asm volatile("ldmatrix.sync.aligned.m8n8.x4.shared.b16 {%0,%1,%2,%3}, [%4];\n"
        : "=r"(r[0]),"=r"(r[1]),"=r"(r[2]),"=r"(r[3]) : "r"(a));
}
__device__ __forceinline__ void ldsm4t(uint32_t r[4], uint32_t a){
    asm volatile("ldmatrix.sync.aligned.m8n8.x4.trans.shared.b16 {%0,%1,%2,%3}, [%4];\n"
        : "=r"(r[0]),"=r"(r[1]),"=r"(r[2]),"=r"(r[3]) : "r"(a));
}
__device__ __forceinline__ void mma16816h(float c[4], const uint32_t a[4], const uint32_t b[2]){
    asm volatile("mma.sync.aligned.m16n8k16.row.col.f32.f16.f16.f32 "
        "{%0,%1,%2,%3}, {%4,%5,%6,%7}, {%8,%9}, {%0,%1,%2,%3};\n"
        : "+f"(c[0]),"+f"(c[1]),"+f"(c[2]),"+f"(c[3])
        : "r"(a[0]),"r"(a[1]),"r"(a[2]),"r"(a[3]),"r"(b[0]),"r"(b[1]));
}
__device__ __forceinline__ void cpasync16(uint32_t dst, const void* src){
    asm volatile("cp.async.cg.shared.global [%0], [%1], 16;\n" :: "r"(dst), "l"(src));
}
__device__ __forceinline__ void cp_commit(){ asm volatile("cp.async.commit_group;\n"); }
__device__ __forceinline__ void cp_wait0(){ asm volatile("cp.async.wait_group 0;\n"); }

// ---------------- weight convert (tiled transpose) + fused stats zero -------
__global__ __launch_bounds__(1024) void prep_w1(const float* __restrict__ W1){
    __shared__ float tile[32][33];
    if (blockIdx.x == 0 && blockIdx.y == 0 && threadIdx.x < 2*CO_){
        g_stats1[threadIdx.x] = 0.f;
        g_stats2[threadIdx.x] = 0.f;
    }
    int k0 = blockIdx.x*32, n0 = blockIdx.y*32;
    int tx = threadIdx.x & 31, ty = threadIdx.x >> 5;
    tile[ty][tx] = W1[(size_t)(n0+ty)*K1_ + k0 + tx];
    __syncthreads();
    g_W1h[(size_t)(k0+ty)*CO_ + n0 + tx] = __float2half_rn(tile[tx][ty]);
}
__global__ __launch_bounds__(1024) void prep_w2(const float* __restrict__ W2){
    __shared__ float tile[32][33];
    int k0 = blockIdx.x*32, n0 = blockIdx.y*32;
    int tx = threadIdx.x & 31, ty = threadIdx.x >> 5;
    tile[ty][tx] = W2[(size_t)(n0+ty)*CO_ + k0 + tx];
    __syncthreads();
    g_W2h[(size_t)(k0+ty)*CO_ + n0 + tx] = __float2half_rn(tile[tx][ty]);
}

// ---------------- 3-NN: 2 threads per query (split-M scan + merge) ----------
__global__ __launch_bounds__(256) void three_nn_kernel(const float* __restrict__ xyz1,
                                                       const float* __restrict__ xyz2){
    __shared__ float4 sq[M_];
    __shared__ float sd[256][3];
    __shared__ int   si[256][3];
    int b = blockIdx.y;
    for (int j = threadIdx.x; j < M_; j += 256){
        const float* p = xyz2 + ((size_t)b*M_ + j)*3;
        float x = p[0], y = p[1], z = p[2];
        sq[j] = make_float4(x, y, z, x*x + y*y + z*z);
    }
    __syncthreads();
    int q    = threadIdx.x & 127;          // query within block
    int hlf  = threadIdx.x >> 7;           // which half of M
    int n    = blockIdx.x*128 + q;
    int bn   = b*N_ + n;
    float px = xyz1[bn*3+0], py = xyz1[bn*3+1], pz = xyz1[bn*3+2];
    float tx = -2.f*px, ty = -2.f*py, tz = -2.f*pz;
    float d0 = 3.4e38f, d1 = 3.4e38f, d2v = 3.4e38f;
    int   i0 = 0, i1 = 0, i2 = 0;
    int j0 = hlf * (M_/2), j1e = j0 + (M_/2);
    #pragma unroll 4
    for (int j = j0; j < j1e; j++){
        float4 qv = sq[j];
        float d = fmaf(tx, qv.x, qv.w);
        d = fmaf(ty, qv.y, d);
        d = fmaf(tz, qv.z, d);
        if (d < d2v){
            if (d < d1){
                d2v = d1; i2 = i1;
                if (d < d0){ d1 = d0; i1 = i0; d0 = d; i0 = j; }
                else       { d1 = d;  i1 = j; }
            } else { d2v = d; i2 = j; }
        }
    }
    sd[threadIdx.x][0] = d0;  sd[threadIdx.x][1] = d1;  sd[threadIdx.x][2] = d2v;
    si[threadIdx.x][0] = i0;  si[threadIdx.x][1] = i1;  si[threadIdx.x][2] = i2;
    __syncthreads();
    if (hlf == 0){
        // merge partner's top-3 (higher j range: strict < keeps lower-index ties)
        #pragma unroll
        for (int t = 0; t < 3; t++){
            float d = sd[q + 128][t];
            int   j = si[q + 128][t];
            if (d < d2v){
                if (d < d1){
                    d2v = d1; i2 = i1;
                    if (d < d0){ d1 = d0; i1 = i0; d0 = d; i0 = j; }
                    else       { d1 = d;  i1 = j; }
                } else { d2v = d; i2 = j; }
            }
        }
        float psq = px*px + py*py + pz*pz;
        float a0 = fminf(fmaxf(d0 + psq, 0.f), 1e-10f);
        float a1 = fminf(fmaxf(d1 + psq, 0.f), 1e-10f);
        float a2 = fminf(fmaxf(d2v + psq, 0.f), 1e-10f);
        float v0 = 1.f/a0, v1 = 1.f/a1, v2 = 1.f/a2;
        float s  = v0 + v1 + v2;
        g_w[bn*3+0] = v0/s; g_w[bn*3+1] = v1/s; g_w[bn*3+2] = v2/s;
        g_idx[bn*3+0] = i0; g_idx[bn*3+1] = i1; g_idx[bn*3+2] = i2;
    }
}

// ---------------- GEMM (fp16x2 split, pass-major mma, 2 CTA/SM) -------------
// Block 128x128, 256 thr, warp grid 4x2, warp tile 32x64.
// y = (Ah + Al) @ Bh   (A split fp16 hi/lo, B single fp16)
// MODE 0: Z  = points2 @ W1[k<512]                      rows=ZR,  KTILES=16
// MODE 1: y1 = points1 @ W1[k>=512] + b1 + sum w_i*Z[idx_i] ; stats1  KTILES=8
// MODE 2: y2 = relu(bn(y1)) @ W2 + b2 ; stats2                        KTILES=8
template<int MODE>
__global__ __launch_bounds__(256, 2) void gemm_kernel(const float* __restrict__ points1,
                                                      const float* __restrict__ points2,
                                                      const float* __restrict__ bias){
    constexpr int KTILES = (MODE == 0) ? 16 : 8;
    constexpr int KOFF   = (MODE == 1) ? 512 : 0;

    extern __shared__ __align__(16) char smem_raw[];
    __half* sA = (__half*)smem_raw;            // [2 stages][hi/lo][128*LDA]
    __half* sB = sA + 2*A_STAGE;               // [2 stages][32*LDB]
    float* s_bias = (float*)(sB + 2*B_STAGE);  // [128]
    float* s_bna  = s_bias + 128;              // [256]
    float* s_bnb  = s_bna + 256;               // [256]
    float* s_sum  = s_bnb + 256;               // [128]
    float* s_sq   = s_sum + 128;               // [128]
    float* s_w3   = s_sq  + 128;               // [384]
    int*   s_i3   = (int*)(s_w3 + 384);        // [384]

    const int tid  = threadIdx.x;
    const int lane = tid & 31;
    const int warp = tid >> 5;
    const int wm   = warp & 3;
    const int wn   = warp >> 2;
    const int mb   = blockIdx.x >> 1;
    const int nb   = blockIdx.x & 1;
    const int row0 = mb * 128;
    const int col0 = nb * 128;

    if (MODE != 0 && tid < 128){
        s_bias[tid] = bias[col0 + tid];
        s_sum[tid] = 0.f; s_sq[tid] = 0.f;
    }
    if (MODE == 2){ s_bna[tid] = g_bn1a[tid]; s_bnb[tid] = g_bn1b[tid]; }
    if (MODE == 1 && tid < 128){
        int bn = row0 + tid;
        #pragma unroll
        for (int j = 0; j < 3; j++){
            s_i3[tid*3+j] = g_idx[bn*3+j];
            s_w3[tid*3+j] = g_w[bn*3+j];
        }
    }
    __syncthreads();

    const int r    = tid >> 1;
    const int half = tid & 1;
    const int bn   = row0 + r;

    const float* rowsrc;
    if      (MODE == 0) rowsrc = points2 + (size_t)bn*C2_ + half*16;
    else if (MODE == 1) rowsrc = points1 + (size_t)bn*C1_ + half*16;
    else                rowsrc = g_y1    + (size_t)bn*CO_ + half*16;

    const __half* gW = (MODE == 2) ? g_W2h : g_W1h;

    const int brow = tid >> 3;
    const int bco  = (tid & 7) * 16;
    const uint32_t sBu = s2u(sB);

    float acc[2][8][4];
    #pragma unroll
    for (int a = 0; a < 2; a++)
        #pragma unroll
        for (int q = 0; q < 8; q++)
            #pragma unroll
            for (int c = 0; c < 4; c++) acc[a][q][c] = 0.f;

    float pr[8];

    auto cpB = [&](int kt, int stage){
        const __half* src = gW + (size_t)(KOFF + kt*32)*CO_ + brow*CO_ + col0 + bco;
        uint32_t dst = sBu + (uint32_t)(stage*B_STAGE + brow*LDB + bco)*2;
        cpasync16(dst,      src);
        cpasync16(dst + 16, src + 8);
    };
    auto issueA = [&](int kt, int c){
        int off = kt*32 + c*8;
        *(float4*)(pr+0) = *(const float4*)(rowsrc + off);
        *(float4*)(pr+4) = *(const float4*)(rowsrc + off + 4);
    };
    auto storeA = [&](int kt, int c, int stage){
        float av[8];
        if (MODE == 2){
            int kg = kt*32 + half*16 + c*8;
            #pragma unroll
            for (int i = 0; i < 8; i++)
                av[i] = fmaxf(fmaf(s_bna[kg+i], pr[i], s_bnb[kg+i]), 0.f);
        } else {
            #pragma unroll
            for (int i = 0; i < 8; i++) av[i] = pr[i];
        }
        uint32_t ph[4], pl[4];
        #pragma unroll
        for (int i = 0; i < 4; i++){
            float e = av[2*i], o = av[2*i+1];
            __half eh = __float2half_rn(e);
            __half oh = __float2half_rn(o);
            __half el = __float2half_rn(e - __half2float(eh));
            __half ol = __float2half_rn(o - __half2float(oh));
            __half2 vh; vh.x = eh; vh.y = oh;
            __half2 vl; vl.x = el; vl.y = ol;
            ph[i] = *(uint32_t*)&vh;
            pl[i] = *(uint32_t*)&vl;
        }
        int eoff = r*LDA + half*16 + c*8;
        *(uint4*)(sA + stage*A_STAGE + eoff)           = make_uint4(ph[0],ph[1],ph[2],ph[3]);
        *(uint4*)(sA + stage*A_STAGE + 128*LDA + eoff) = make_uint4(pl[0],pl[1],pl[2],pl[3]);
    };
    auto compute_half = [&](int stage, int ks){
        const __half* pAh = sA + stage*A_STAGE;
        const __half* pAl = pAh + 128*LDA;
        const __half* pB  = sB + stage*B_STAGE;
        uint32_t ah[2][4], al[2][4];
        #pragma unroll
        for (int mi = 0; mi < 2; mi++){
            int arow = wm*32 + mi*16 + (lane & 15);
            int acol = ks + ((lane >> 4) << 3);
            ldsm4(ah[mi], s2u(pAh + arow*LDA + acol));
            ldsm4(al[mi], s2u(pAl + arow*LDA + acol));
        }
        int rk = ks + (lane & 7) + (lane & 8);
        #pragma unroll
        for (int g = 0; g < 4; g++){
            uint32_t bh[4];
            int cb = wn*64 + g*16 + ((lane >> 4) << 3);
            ldsm4t(bh, s2u(pB + rk*LDB + cb));
            // pass-major: 4 independent accumulators between dependent mmas
            #pragma unroll
            for (int mi = 0; mi < 2; mi++)
                #pragma unroll
                for (int sub = 0; sub < 2; sub++)
                    mma16816h(acc[mi][g*2+sub], ah[mi], &bh[sub*2]);  // hi
            #pragma unroll
            for (int mi = 0; mi < 2; mi++)
                #pragma unroll
                for (int sub = 0; sub < 2; sub++)
                    mma16816h(acc[mi][g*2+sub], al[mi], &bh[sub*2]);  // lo
        }
    };

    // ---- prologue ----
    cpB(0, 0); cp_commit();
    issueA(0, 0); storeA(0, 0, 0);
    issueA(0, 1); storeA(0, 1, 0);
    cp_wait0();
    __syncthreads();

    // ---- main loop ----
    for (int kt = 0; kt < KTILES; kt++){
        int cur = kt & 1, nxt = cur ^ 1;
        bool pf = (kt + 1 < KTILES);
        if (pf){ cpB(kt + 1, nxt); cp_commit(); issueA(kt + 1, 0); }
        compute_half(cur, 0);
        if (pf){ storeA(kt + 1, 0, nxt); issueA(kt + 1, 1); }
        compute_half(cur, 16);
        if (pf){ storeA(kt + 1, 1, nxt); }
        cp_wait0();
        __syncthreads();
    }

    // ---- epilogue ----
    float* yout = (MODE == 0) ? g_z : (MODE == 1) ? g_y1 : g_y2;
    const float* zb = g_z + (size_t)(row0 >> 12) * (M_*CO_);

    #pragma unroll
    for (int mi = 0; mi < 2; mi++){
        int lrA = wm*32 + mi*16 + (lane >> 2);
        int lrB = lrA + 8;
        const float *zA0=nullptr,*zA1=nullptr,*zA2=nullptr,*zB0=nullptr,*zB1=nullptr,*zB2=nullptr;
        float wA0=0,wA1=0,wA2=0,wB0=0,wB1=0,wB2=0;
        if (MODE == 1){
            zA0 = zb + (size_t)s_i3[lrA*3+0]*CO_; wA0 = s_w3[lrA*3+0];
            zA1 = zb + (size_t)s_i3[lrA*3+1]*CO_; wA1 = s_w3[lrA*3+1];
            zA2 = zb + (size_t)s_i3[lrA*3+2]*CO_; wA2 = s_w3[lrA*3+2];
            zB0 = zb + (size_t)s_i3[lrB*3+0]*CO_; wB0 = s_w3[lrB*3+0];
            zB1 = zb + (size_t)s_i3[lrB*3+1]*CO_; wB1 = s_w3[lrB*3+1];
            zB2 = zb + (size_t)s_i3[lrB*3+2]*CO_; wB2 = s_w3[lrB*3+2];
        }
        #pragma unroll
        for (int ni = 0; ni < 8; ni++){
            int lc = wn*64 + ni*8 + ((lane & 3) << 1);
            int gc = col0 + lc;
            float v0 = acc[mi][ni][0], v1 = acc[mi][ni][1];
            float v2 = acc[mi][ni][2], v3 = acc[mi][ni][3];
            if (MODE != 0){
                float b0 = s_bias[lc], b1 = s_bias[lc+1];
                v0 += b0; v1 += b1; v2 += b0; v3 += b1;
            }
            if (MODE == 1){
                float2 a0 = *(const float2*)(zA0 + gc);
                float2 a1 = *(const float2*)(zA1 + gc);
                float2 a2 = *(const float2*)(zA2 + gc);
                v0 += wA0*a0.x + wA1*a1.x + wA2*a2.x;
                v1 += wA0*a0.y + wA1*a1.y + wA2*a2.y;
                float2 c0 = *(const float2*)(zB0 + gc);
                float2 c1 = *(const float2*)(zB1 + gc);
                float2 c2 = *(const float2*)(zB2 + gc);
                v2 += wB0*c0.x + wB1*c1.x + wB2*c2.x;
                v3 += wB0*c0.y + wB1*c1.y + wB2*c2.y;
            }
            float2 p;
            p.x = v0; p.y = v1;
            *(float2*)(yout + (size_t)(row0 + lrA)*CO_ + gc) = p;
            p.x = v2; p.y = v3;
            *(float2*)(yout + (size_t)(row0 + lrB)*CO_ + gc) = p;
            if (MODE != 0){
                float sum0 = v0 + v2, sq0 = v0*v0 + v2*v2;
                float sum1 = v1 + v3, sq1 = v1*v1 + v3*v3;
                #pragma unroll
                for (int o = 4; o < 32; o <<= 1){
                    sum0 += __shfl_xor_sync(0xFFFFFFFFu, sum0, o);
                    sq0  += __shfl_xor_sync(0xFFFFFFFFu, sq0,  o);
                    sum1 += __shfl_xor_sync(0xFFFFFFFFu, sum1, o);
                    sq1  += __shfl_xor_sync(0xFFFFFFFFu, sq1,  o);
                }
                if (lane < 4){
                    atomicAdd(&s_sum[lc],   sum0);
                    atomicAdd(&s_sq[lc],    sq0);
                    atomicAdd(&s_sum[lc+1], sum1);
                    atomicAdd(&s_sq[lc+1],  sq1);
                }
            }
        }
    }
    if (MODE != 0){
        float* gst = (MODE == 1) ? g_stats1 : g_stats2;
        __syncthreads();
        if (tid < 128){
            atomicAdd(&gst[col0 + tid],       s_sum[tid]);
            atomicAdd(&gst[CO_ + col0 + tid], s_sq[tid]);
        }
    }
}

// ---------------- BN finalize ----------------------------------------------
template<int L>
__global__ void bnfin_kernel(const float* __restrict__ g, const float* __restrict__ beta){
    int c = threadIdx.x;
    const float* st = (L == 1) ? g_stats1 : g_stats2;
    float* pa = (L == 1) ? g_bn1a : g_bn2a;
    float* pb = (L == 1) ? g_bn1b : g_bn2b;
    const float invN = 1.f / (float)BNR;
    float mean = st[c] * invN;
    float var  = st[CO_ + c] * invN - mean*mean;
    float a = g[c] / sqrtf(var + 1e-5f);
    pa[c] = a;
    pb[c] = beta[c] - mean*a;
}

// ---------------- BN2 + relu + transpose to (b, c, n) -----------------------
__global__ __launch_bounds__(256) void out_kernel(float* __restrict__ out){
    __shared__ float s[32][33];
    int b  = blockIdx.z;
    int n0 = blockIdx.x * 32, c0 = blockIdx.y * 32;
    int tx = threadIdx.x & 31, ty = threadIdx.x >> 5;   // ty 0..7
    #pragma unroll
    for (int k = 0; k < 4; k++){
        int row = ty + k*8;
        float v = g_y2[(size_t)(b*N_ + n0 + row)*CO_ + c0 + tx];
        float a = g_bn2a[c0 + tx], bb = g_bn2b[c0 + tx];
        s[row][tx] = fmaxf(fmaf(a, v, bb), 0.f);
    }
    __syncthreads();
    #pragma unroll
    for (int k = 0; k < 4; k++){
        int row = ty + k*8;
        out[(size_t)(b*CO_ + c0 + row)*N_ + n0 + tx] = s[tx][row];
    }
}

// ---------------- launch ----------------------------------------------------
extern "C" void kernel_launch(void* const* d_in, const int* in_sizes, int n_in,
                              void* d_out, int out_size){
    const float* xyz1    = (const float*)d_in[0];
    const float* xyz2    = (const float*)d_in[1];
    const float* points1 = (const float*)d_in[2];
    const float* points2 = (const float*)d_in[3];
    const float* W1      = (const float*)d_in[4];
    const float* b1      = (const float*)d_in[5];
    const float* g1      = (const float*)d_in[6];
    const float* beta1   = (const float*)d_in[7];
    const float* W2      = (const float*)d_in[8];
    const float* b2      = (const float*)d_in[9];
    const float* g2      = (const float*)d_in[10];
    const float* beta2   = (const float*)d_in[11];
    float* out = (float*)d_out;

    cudaFuncSetAttribute(gemm_kernel<0>, cudaFuncAttributeMaxDynamicSharedMemorySize, SMEM_BYTES);
    cudaFuncSetAttribute(gemm_kernel<1>, cudaFuncAttributeMaxDynamicSharedMemorySize, SMEM_BYTES);
    cudaFuncSetAttribute(gemm_kernel<2>, cudaFuncAttributeMaxDynamicSharedMemorySize, SMEM_BYTES);

    prep_w1<<<dim3(24, 8), 1024>>>(W1);
    prep_w2<<<dim3(8, 8), 1024>>>(W2);
    three_nn_kernel<<<dim3(32, 16), 256>>>(xyz1, xyz2);

    gemm_kernel<0><<<256, 256, SMEM_BYTES>>>(points1, points2, nullptr);  // Z
    gemm_kernel<1><<<1024, 256, SMEM_BYTES>>>(points1, points2, b1);      // y1
    bnfin_kernel<1><<<1, 256>>>(g1, beta1);

    gemm_kernel<2><<<1024, 256, SMEM_BYTES>>>(points1, points2, b2);      // y2
    bnfin_kernel<2><<<1, 256>>>(g2, beta2);

    out_kernel<<<dim3(128, 8, 16), 256>>>(out);
}